// round 4
// baseline (speedup 1.0000x reference)
#include <cuda_runtime.h>
#include <cuda_bf16.h>

#define N_NODES 50000
#define D 16
#define H 64

__device__ float g_acc[N_NODES * D];
__device__ float g_deg[N_NODES];

__global__ void init_kernel() {
    int idx = blockIdx.x * blockDim.x + threadIdx.x;
    int total = N_NODES * D + N_NODES;
    if (idx < N_NODES * D) {
        g_acc[idx] = 0.0f;
    } else if (idx < total) {
        g_deg[idx - N_NODES * D] = 0.0f;
    }
}

__global__ void deg_kernel(const int* __restrict__ ei, int E) {
    int e = blockIdx.x * blockDim.x + threadIdx.x;
    if (e >= E) return;
    int s = ei[e];
    int d = ei[E + e];
    atomicAdd(&g_deg[s], 1.0f);
    atomicAdd(&g_deg[d], 1.0f);
}

// Compute v = W2 @ relu(W1 @ [a;b] + b1) + b2
__device__ __forceinline__ void reflect_mlp(
    const float* __restrict__ a, const float* __restrict__ b,
    const float* __restrict__ w1s, const float* __restrict__ w2ts,
    const float* __restrict__ b1s, const float* __restrict__ b2s,
    float* __restrict__ v)
{
#pragma unroll
    for (int i = 0; i < D; i++) v[i] = b2s[i];

#pragma unroll 4
    for (int j = 0; j < H; j++) {
        const float* w = &w1s[j * 32];
        float h0 = b1s[j], h1 = 0.f, h2 = 0.f, h3 = 0.f;
#pragma unroll
        for (int k = 0; k < D; k += 4) {
            h0 = fmaf(w[k + 0], a[k + 0], h0);
            h1 = fmaf(w[k + 1], a[k + 1], h1);
            h2 = fmaf(w[k + 2], a[k + 2], h2);
            h3 = fmaf(w[k + 3], a[k + 3], h3);
        }
#pragma unroll
        for (int k = 0; k < D; k += 4) {
            h0 = fmaf(w[16 + k + 0], b[k + 0], h0);
            h1 = fmaf(w[16 + k + 1], b[k + 1], h1);
            h2 = fmaf(w[16 + k + 2], b[k + 2], h2);
            h3 = fmaf(w[16 + k + 3], b[k + 3], h3);
        }
        float h = fmaxf((h0 + h1) + (h2 + h3), 0.0f);
        const float* w2 = &w2ts[j * D];
#pragma unroll
        for (int i = 0; i < D; i++) v[i] = fmaf(w2[i], h, v[i]);
    }
}

__global__ __launch_bounds__(128)
void edge_kernel(const float* __restrict__ x, const int* __restrict__ ei,
                 const float* __restrict__ W1, const float* __restrict__ b1,
                 const float* __restrict__ W2, const float* __restrict__ b2, int E)
{
    __shared__ float w1s[H * 32];   // W1 row-major [H][32]
    __shared__ float w2ts[H * D];   // W2 transposed: w2ts[j][i] = W2[i][j]
    __shared__ float b1s[H];
    __shared__ float b2s[D];

    for (int i = threadIdx.x; i < H * 32; i += blockDim.x) w1s[i] = W1[i];
    for (int i = threadIdx.x; i < H * D; i += blockDim.x) {
        int j = i / D, ii = i % D;
        w2ts[i] = W2[ii * H + j];
    }
    if (threadIdx.x < H) b1s[threadIdx.x] = b1[threadIdx.x];
    if (threadIdx.x < D) b2s[threadIdx.x] = b2[threadIdx.x];
    __syncthreads();

    int e = blockIdx.x * blockDim.x + threadIdx.x;
    if (e >= E) return;

    int s = ei[e];
    int d = ei[E + e];

    float xs[D], xd[D];
    {
        const float4* ps = (const float4*)(x + (size_t)s * D);
        const float4* pd = (const float4*)(x + (size_t)d * D);
#pragma unroll
        for (int q = 0; q < 4; q++) {
            float4 v4 = ps[q];
            xs[4 * q + 0] = v4.x; xs[4 * q + 1] = v4.y;
            xs[4 * q + 2] = v4.z; xs[4 * q + 3] = v4.w;
            float4 w4 = pd[q];
            xd[4 * q + 0] = w4.x; xd[4 * q + 1] = w4.y;
            xd[4 * q + 2] = w4.z; xd[4 * q + 3] = w4.w;
        }
    }

    // u = normalize(MLP(xs ; xd))
    float u[D];
    reflect_mlp(xs, xd, w1s, w2ts, b1s, b2s, u);
    {
        float n2 = 0.f;
#pragma unroll
        for (int i = 0; i < D; i++) n2 = fmaf(u[i], u[i], n2);
        float inv = 1.0f / fmaxf(sqrtf(n2), 1e-12f);
#pragma unroll
        for (int i = 0; i < D; i++) u[i] *= inv;
    }

    // w = normalize(MLP(xd ; xs))
    float w[D];
    reflect_mlp(xd, xs, w1s, w2ts, b1s, b2s, w);
    {
        float n2 = 0.f;
#pragma unroll
        for (int i = 0; i < D; i++) n2 = fmaf(w[i], w[i], n2);
        float inv = 1.0f / fmaxf(sqrtf(n2), 1e-12f);
#pragma unroll
        for (int i = 0; i < D; i++) w[i] *= inv;
    }

    // dot products
    float uw = 0.f, u_xd = 0.f, w_xd = 0.f, u_xs = 0.f, w_xs = 0.f;
#pragma unroll
    for (int i = 0; i < D; i++) {
        uw   = fmaf(u[i], w[i],  uw);
        u_xd = fmaf(u[i], xd[i], u_xd);
        w_xd = fmaf(w[i], xd[i], w_xd);
        u_xs = fmaf(u[i], xs[i], u_xs);
        w_xs = fmaf(w[i], xs[i], w_xs);
    }

    float dis = rsqrtf(fmaxf(g_deg[s], 1e-5f));
    float did = rsqrtf(fmaxf(g_deg[d], 1e-5f));
    float coef = dis * did;

    // F_s = I - 2uu^T, F_d = I - 2ww^T, L = -F_s^T F_d
    // msg_s = -coef * ( xd + cu_s*u + cw_s*w ),  scattered to src
    float cu_s = -2.0f * u_xd + 4.0f * uw * w_xd;
    float cw_s = -2.0f * w_xd;
    // msg_d = -coef * ( xs + cu_d*u + cw_d*w ),  scattered to dst
    float cu_d = -2.0f * u_xs;
    float cw_d = -2.0f * w_xs + 4.0f * uw * u_xs;

    float* accs = &g_acc[(size_t)s * D];
    float* accd = &g_acc[(size_t)d * D];
#pragma unroll
    for (int i = 0; i < D; i++) {
        float ms = -coef * (xd[i] + cu_s * u[i] + cw_s * w[i]);
        atomicAdd(&accs[i], ms);
    }
#pragma unroll
    for (int i = 0; i < D; i++) {
        float md = -coef * (xs[i] + cu_d * u[i] + cw_d * w[i]);
        atomicAdd(&accd[i], md);
    }
}

__global__ void out_kernel(const float* __restrict__ x, float* __restrict__ out, int n) {
    int idx = blockIdx.x * blockDim.x + threadIdx.x;
    if (idx >= n) return;
    out[idx] = fmaxf(x[idx] - g_acc[idx], 0.0f);
}

extern "C" void kernel_launch(void* const* d_in, const int* in_sizes, int n_in,
                              void* d_out, int out_size) {
    const float* x  = (const float*)d_in[0];
    const int*   ei = (const int*)d_in[1];   // edge_index is int32 (JAX x64 disabled)
    const float* W1 = (const float*)d_in[2];
    const float* b1 = (const float*)d_in[3];
    const float* W2 = (const float*)d_in[4];
    const float* b2 = (const float*)d_in[5];
    float* out = (float*)d_out;

    int E = in_sizes[1] / 2;          // edge_index has 2*E entries
    int n = in_sizes[0];              // N_NODES * D floats

    int initTotal = N_NODES * D + N_NODES;
    init_kernel<<<(initTotal + 255) / 256, 256>>>();
    deg_kernel<<<(E + 255) / 256, 256>>>(ei, E);
    edge_kernel<<<(E + 127) / 128, 128>>>(x, ei, W1, b1, W2, b2, E);
    out_kernel<<<(n + 255) / 256, 256>>>(x, out, n);
}

// round 5
// speedup vs baseline: 1.3713x; 1.3713x over previous
#include <cuda_runtime.h>
#include <cuda_bf16.h>

#define N_NODES 50000
#define D 16
#define H 64

__device__ float g_acc[N_NODES * D];
__device__ float g_deg[N_NODES];
// Per-node precomputed first-layer partials: [n][0:64)=P=W1a@x[n], [n][64:128)=Q=W1b@x[n]
__device__ float g_PQ[N_NODES * 2 * H];

__global__ void init_kernel() {
    int idx = blockIdx.x * blockDim.x + threadIdx.x;
    int total = N_NODES * D + N_NODES;
    if (idx < N_NODES * D) {
        g_acc[idx] = 0.0f;
    } else if (idx < total) {
        g_deg[idx - N_NODES * D] = 0.0f;
    }
}

__global__ void deg_kernel(const int* __restrict__ ei, int E) {
    int e = blockIdx.x * blockDim.x + threadIdx.x;
    if (e >= E) return;
    atomicAdd(&g_deg[ei[e]], 1.0f);
    atomicAdd(&g_deg[ei[E + e]], 1.0f);
}

// Per-node: P[j] = sum_k W1[j][k]   * x[n][k]
//           Q[j] = sum_k W1[j][16+k]* x[n][k]
__global__ __launch_bounds__(128)
void node_kernel(const float* __restrict__ x, const float* __restrict__ W1, int n_nodes)
{
    __shared__ float w1s[H * 32];
    for (int i = threadIdx.x; i < H * 32; i += blockDim.x) w1s[i] = W1[i];
    __syncthreads();

    int n = blockIdx.x * blockDim.x + threadIdx.x;
    if (n >= n_nodes) return;

    float xv[D];
    const float4* px = (const float4*)(x + (size_t)n * D);
#pragma unroll
    for (int q = 0; q < 4; q++) {
        float4 v4 = px[q];
        xv[4 * q + 0] = v4.x; xv[4 * q + 1] = v4.y;
        xv[4 * q + 2] = v4.z; xv[4 * q + 3] = v4.w;
    }

    float* pq = &g_PQ[(size_t)n * 2 * H];
#pragma unroll 4
    for (int jg = 0; jg < H / 4; jg++) {
        float p[4], qv[4];
#pragma unroll
        for (int jj = 0; jj < 4; jj++) {
            const float* w = &w1s[(jg * 4 + jj) * 32];
            float p0 = 0.f, p1 = 0.f, q0 = 0.f, q1 = 0.f;
#pragma unroll
            for (int k = 0; k < D; k += 2) {
                p0 = fmaf(w[k],          xv[k],     p0);
                p1 = fmaf(w[k + 1],      xv[k + 1], p1);
                q0 = fmaf(w[16 + k],     xv[k],     q0);
                q1 = fmaf(w[16 + k + 1], xv[k + 1], q1);
            }
            p[jj] = p0 + p1;
            qv[jj] = q0 + q1;
        }
        *(float4*)(pq + jg * 4)     = make_float4(p[0], p[1], p[2], p[3]);
        *(float4*)(pq + H + jg * 4) = make_float4(qv[0], qv[1], qv[2], qv[3]);
    }
}

__device__ __forceinline__ void red_add_v4(float* addr, float a, float b, float c, float d) {
    asm volatile("red.global.add.v4.f32 [%0], {%1, %2, %3, %4};"
                 :: "l"(addr), "f"(a), "f"(b), "f"(c), "f"(d) : "memory");
}

__global__ __launch_bounds__(128)
void edge_kernel(const float* __restrict__ x, const int* __restrict__ ei,
                 const float* __restrict__ b1, const float* __restrict__ W2,
                 const float* __restrict__ b2, int E)
{
    __shared__ float w2ts[H * D];   // w2ts[j][i] = W2[i][j]
    __shared__ float b1s[H];
    __shared__ float b2s[D];

    for (int i = threadIdx.x; i < H * D; i += blockDim.x) {
        int j = i / D, ii = i % D;
        w2ts[i] = W2[ii * H + j];
    }
    if (threadIdx.x < H) b1s[threadIdx.x] = b1[threadIdx.x];
    if (threadIdx.x < D) b2s[threadIdx.x] = b2[threadIdx.x];
    __syncthreads();

    int e = blockIdx.x * blockDim.x + threadIdx.x;
    if (e >= E) return;

    int s = ei[e];
    int d = ei[E + e];

    const float4* Ps = (const float4*)&g_PQ[(size_t)s * 2 * H];
    const float4* Qs = Ps + H / 4;
    const float4* Pd = (const float4*)&g_PQ[(size_t)d * 2 * H];
    const float4* Qd = Pd + H / 4;

    // u-dir: h_u = relu(P[s] + Q[d] + b1); w-dir: h_w = relu(P[d] + Q[s] + b1)
    float vu[D], vw[D];
#pragma unroll
    for (int i = 0; i < D; i++) { vu[i] = b2s[i]; vw[i] = b2s[i]; }

#pragma unroll 4
    for (int g = 0; g < H / 4; g++) {
        float4 ps = Ps[g], qd = Qd[g], pd = Pd[g], qs = Qs[g];
        const float* bb = &b1s[g * 4];
        float hu0 = fmaxf(ps.x + qd.x + bb[0], 0.f);
        float hu1 = fmaxf(ps.y + qd.y + bb[1], 0.f);
        float hu2 = fmaxf(ps.z + qd.z + bb[2], 0.f);
        float hu3 = fmaxf(ps.w + qd.w + bb[3], 0.f);
        float hw0 = fmaxf(pd.x + qs.x + bb[0], 0.f);
        float hw1 = fmaxf(pd.y + qs.y + bb[1], 0.f);
        float hw2 = fmaxf(pd.z + qs.z + bb[2], 0.f);
        float hw3 = fmaxf(pd.w + qs.w + bb[3], 0.f);
        const float* w20 = &w2ts[(g * 4 + 0) * D];
        const float* w21 = &w2ts[(g * 4 + 1) * D];
        const float* w22 = &w2ts[(g * 4 + 2) * D];
        const float* w23 = &w2ts[(g * 4 + 3) * D];
#pragma unroll
        for (int i = 0; i < D; i++) {
            float a0 = w20[i], a1 = w21[i], a2 = w22[i], a3 = w23[i];
            vu[i] = fmaf(a0, hu0, vu[i]);
            vu[i] = fmaf(a1, hu1, vu[i]);
            vu[i] = fmaf(a2, hu2, vu[i]);
            vu[i] = fmaf(a3, hu3, vu[i]);
            vw[i] = fmaf(a0, hw0, vw[i]);
            vw[i] = fmaf(a1, hw1, vw[i]);
            vw[i] = fmaf(a2, hw2, vw[i]);
            vw[i] = fmaf(a3, hw3, vw[i]);
        }
    }

    // normalize u (=vu), w (=vw)
    float n2u = 0.f, n2w = 0.f;
#pragma unroll
    for (int i = 0; i < D; i++) {
        n2u = fmaf(vu[i], vu[i], n2u);
        n2w = fmaf(vw[i], vw[i], n2w);
    }
    float invu = 1.0f / fmaxf(sqrtf(n2u), 1e-12f);
    float invw = 1.0f / fmaxf(sqrtf(n2w), 1e-12f);
#pragma unroll
    for (int i = 0; i < D; i++) { vu[i] *= invu; vw[i] *= invw; }

    // load xs, xd (after MLP to shrink live range)
    float xs[D], xd[D];
    {
        const float4* pxs = (const float4*)(x + (size_t)s * D);
        const float4* pxd = (const float4*)(x + (size_t)d * D);
#pragma unroll
        for (int q = 0; q < 4; q++) {
            float4 v4 = pxs[q];
            xs[4 * q + 0] = v4.x; xs[4 * q + 1] = v4.y;
            xs[4 * q + 2] = v4.z; xs[4 * q + 3] = v4.w;
            float4 w4 = pxd[q];
            xd[4 * q + 0] = w4.x; xd[4 * q + 1] = w4.y;
            xd[4 * q + 2] = w4.z; xd[4 * q + 3] = w4.w;
        }
    }

    float uw = 0.f, u_xd = 0.f, w_xd = 0.f, u_xs = 0.f, w_xs = 0.f;
#pragma unroll
    for (int i = 0; i < D; i++) {
        uw   = fmaf(vu[i], vw[i], uw);
        u_xd = fmaf(vu[i], xd[i], u_xd);
        w_xd = fmaf(vw[i], xd[i], w_xd);
        u_xs = fmaf(vu[i], xs[i], u_xs);
        w_xs = fmaf(vw[i], xs[i], w_xs);
    }

    float coef = rsqrtf(fmaxf(g_deg[s], 1e-5f)) * rsqrtf(fmaxf(g_deg[d], 1e-5f));

    // F_s = I-2uu^T, F_d = I-2ww^T, L = -F_s^T F_d
    float cu_s = -2.0f * u_xd + 4.0f * uw * w_xd;
    float cw_s = -2.0f * w_xd;
    float cu_d = -2.0f * u_xs;
    float cw_d = -2.0f * w_xs + 4.0f * uw * u_xs;

    float* accs = &g_acc[(size_t)s * D];
    float* accd = &g_acc[(size_t)d * D];
#pragma unroll
    for (int q = 0; q < 4; q++) {
        float m0 = -coef * (xd[4*q+0] + cu_s * vu[4*q+0] + cw_s * vw[4*q+0]);
        float m1 = -coef * (xd[4*q+1] + cu_s * vu[4*q+1] + cw_s * vw[4*q+1]);
        float m2 = -coef * (xd[4*q+2] + cu_s * vu[4*q+2] + cw_s * vw[4*q+2]);
        float m3 = -coef * (xd[4*q+3] + cu_s * vu[4*q+3] + cw_s * vw[4*q+3]);
        red_add_v4(accs + 4 * q, m0, m1, m2, m3);
    }
#pragma unroll
    for (int q = 0; q < 4; q++) {
        float m0 = -coef * (xs[4*q+0] + cu_d * vu[4*q+0] + cw_d * vw[4*q+0]);
        float m1 = -coef * (xs[4*q+1] + cu_d * vu[4*q+1] + cw_d * vw[4*q+1]);
        float m2 = -coef * (xs[4*q+2] + cu_d * vu[4*q+2] + cw_d * vw[4*q+2]);
        float m3 = -coef * (xs[4*q+3] + cu_d * vu[4*q+3] + cw_d * vw[4*q+3]);
        red_add_v4(accd + 4 * q, m0, m1, m2, m3);
    }
}

__global__ void out_kernel(const float* __restrict__ x, float* __restrict__ out, int n) {
    int idx = blockIdx.x * blockDim.x + threadIdx.x;
    if (idx >= n) return;
    out[idx] = fmaxf(x[idx] - g_acc[idx], 0.0f);
}

extern "C" void kernel_launch(void* const* d_in, const int* in_sizes, int n_in,
                              void* d_out, int out_size) {
    const float* x  = (const float*)d_in[0];
    const int*   ei = (const int*)d_in[1];   // edge_index is int32 (JAX x64 disabled)
    const float* W1 = (const float*)d_in[2];
    const float* b1 = (const float*)d_in[3];
    const float* W2 = (const float*)d_in[4];
    const float* b2 = (const float*)d_in[5];
    float* out = (float*)d_out;

    int E = in_sizes[1] / 2;
    int n = in_sizes[0];
    int n_nodes = n / D;

    int initTotal = N_NODES * D + N_NODES;
    init_kernel<<<(initTotal + 255) / 256, 256>>>();
    deg_kernel<<<(E + 255) / 256, 256>>>(ei, E);
    node_kernel<<<(n_nodes + 127) / 128, 128>>>(x, W1, n_nodes);
    edge_kernel<<<(E + 127) / 128, 128>>>(x, ei, b1, W2, b2, E);
    out_kernel<<<(n + 255) / 256, 256>>>(x, out, n);
}